// round 12
// baseline (speedup 1.0000x reference)
#include <cuda_runtime.h>
#include <math.h>

// ---------------------------------------------------------------------------
// Persistent fused kernel, R1-style memory path (plain cached LDG.128 /
// plain STG.128 — no streaming hints: uncoalesced lanes re-reference lines,
// so L1/L2 caching of the X stream is load-bearing).
//   - grid = #SMs * 6 blocks of 256 threads, grid-stride over row-quads.
//   - Prologue once per block: thread 0 composes the 5 tiny linears
//     (7->5->4->3->2->1) into one 7->1 affine map, fully unrolled scalars.
//   - Loop: 4 rows/thread = 7x LDG.128 + 28 FMA + 4 sigmoid + 1x STG.128.
// ---------------------------------------------------------------------------

__global__ void __launch_bounds__(256)
mlp_persist2_kernel(const float* __restrict__ X, float* __restrict__ out, int nrows,
                    const float* __restrict__ W1, const float* __restrict__ b1,
                    const float* __restrict__ W2, const float* __restrict__ b2,
                    const float* __restrict__ W3, const float* __restrict__ b3,
                    const float* __restrict__ W4, const float* __restrict__ b4,
                    const float* __restrict__ W5, const float* __restrict__ b5)
{
    __shared__ float s_weff[8];

    if (threadIdx.x == 0) {
        // ---- fully unrolled compose, scalar registers only ----
        const float c50 = W5[0], c51 = W5[1];

        const float w45_0 = fmaf(W4[0], c50, W4[1] * c51);
        const float w45_1 = fmaf(W4[2], c50, W4[3] * c51);
        const float w45_2 = fmaf(W4[4], c50, W4[5] * c51);

        const float w345_0 = fmaf(W3[0],  w45_0, fmaf(W3[1],  w45_1, W3[2]  * w45_2));
        const float w345_1 = fmaf(W3[3],  w45_0, fmaf(W3[4],  w45_1, W3[5]  * w45_2));
        const float w345_2 = fmaf(W3[6],  w45_0, fmaf(W3[7],  w45_1, W3[8]  * w45_2));
        const float w345_3 = fmaf(W3[9],  w45_0, fmaf(W3[10], w45_1, W3[11] * w45_2));

        const float w2345_0 = fmaf(W2[0],  w345_0, fmaf(W2[1],  w345_1, fmaf(W2[2],  w345_2, W2[3]  * w345_3)));
        const float w2345_1 = fmaf(W2[4],  w345_0, fmaf(W2[5],  w345_1, fmaf(W2[6],  w345_2, W2[7]  * w345_3)));
        const float w2345_2 = fmaf(W2[8],  w345_0, fmaf(W2[9],  w345_1, fmaf(W2[10], w345_2, W2[11] * w345_3)));
        const float w2345_3 = fmaf(W2[12], w345_0, fmaf(W2[13], w345_1, fmaf(W2[14], w345_2, W2[15] * w345_3)));
        const float w2345_4 = fmaf(W2[16], w345_0, fmaf(W2[17], w345_1, fmaf(W2[18], w345_2, W2[19] * w345_3)));

        #pragma unroll
        for (int i = 0; i < 7; i++) {
            s_weff[i] = fmaf(W1[i*5 + 0], w2345_0,
                        fmaf(W1[i*5 + 1], w2345_1,
                        fmaf(W1[i*5 + 2], w2345_2,
                        fmaf(W1[i*5 + 3], w2345_3,
                             W1[i*5 + 4] * w2345_4))));
        }

        float be = b5[0];
        be = fmaf(b4[0], c50, be);
        be = fmaf(b4[1], c51, be);
        be = fmaf(b3[0], w45_0, be);
        be = fmaf(b3[1], w45_1, be);
        be = fmaf(b3[2], w45_2, be);
        be = fmaf(b2[0], w345_0, be);
        be = fmaf(b2[1], w345_1, be);
        be = fmaf(b2[2], w345_2, be);
        be = fmaf(b2[3], w345_3, be);
        be = fmaf(b1[0], w2345_0, be);
        be = fmaf(b1[1], w2345_1, be);
        be = fmaf(b1[2], w2345_2, be);
        be = fmaf(b1[3], w2345_3, be);
        be = fmaf(b1[4], w2345_4, be);
        s_weff[7] = be;
    }
    __syncthreads();

    const float w0 = s_weff[0], w1 = s_weff[1], w2 = s_weff[2], w3 = s_weff[3];
    const float w4 = s_weff[4], w5 = s_weff[5], w6 = s_weff[6], be = s_weff[7];

    const long long nquads = (long long)(nrows >> 2);
    const long long stride = (long long)gridDim.x * blockDim.x;

    const float4* Xv   = reinterpret_cast<const float4*>(X);
    float4*       outv = reinterpret_cast<float4*>(out);

    for (long long i = (long long)blockIdx.x * blockDim.x + threadIdx.x;
         i < nquads; i += stride)
    {
        // 4 rows = 28 consecutive floats; base byte offset 112*i -> 16B aligned
        const float4* src = Xv + i * 7;
        float4 p0 = src[0], p1 = src[1], p2 = src[2], p3 = src[3];
        float4 p4 = src[4], p5 = src[5], p6 = src[6];

        float f[28];
        f[0]=p0.x; f[1]=p0.y; f[2]=p0.z; f[3]=p0.w;
        f[4]=p1.x; f[5]=p1.y; f[6]=p1.z; f[7]=p1.w;
        f[8]=p2.x; f[9]=p2.y; f[10]=p2.z; f[11]=p2.w;
        f[12]=p3.x; f[13]=p3.y; f[14]=p3.z; f[15]=p3.w;
        f[16]=p4.x; f[17]=p4.y; f[18]=p4.z; f[19]=p4.w;
        f[20]=p5.x; f[21]=p5.y; f[22]=p5.z; f[23]=p5.w;
        f[24]=p6.x; f[25]=p6.y; f[26]=p6.z; f[27]=p6.w;

        float r[4];
        #pragma unroll
        for (int r4 = 0; r4 < 4; r4++) {
            const float* x = f + r4 * 7;
            float z = be;
            z = fmaf(x[0], w0, z);
            z = fmaf(x[1], w1, z);
            z = fmaf(x[2], w2, z);
            z = fmaf(x[3], w3, z);
            z = fmaf(x[4], w4, z);
            z = fmaf(x[5], w5, z);
            z = fmaf(x[6], w6, z);
            r[r4] = 1.0f / (1.0f + __expf(-z));
        }

        float4 o;
        o.x = r[0]; o.y = r[1]; o.z = r[2]; o.w = r[3];
        outv[i] = o;
    }

    // Tail rows (nrows % 4) — zero for 4M rows; kept for safety.
    if (blockIdx.x == 0 && threadIdx.x == 0) {
        for (long long rr = (long long)(nrows & ~3); rr < nrows; rr++) {
            const float* x = X + rr * 7;
            float z = be;
            z = fmaf(x[0], w0, z);
            z = fmaf(x[1], w1, z);
            z = fmaf(x[2], w2, z);
            z = fmaf(x[3], w3, z);
            z = fmaf(x[4], w4, z);
            z = fmaf(x[5], w5, z);
            z = fmaf(x[6], w6, z);
            out[rr] = 1.0f / (1.0f + __expf(-z));
        }
    }
}

extern "C" void kernel_launch(void* const* d_in, const int* in_sizes, int n_in,
                              void* d_out, int out_size)
{
    const float* X  = (const float*)d_in[0];
    const float* W1 = (const float*)d_in[1];
    const float* b1 = (const float*)d_in[2];
    const float* W2 = (const float*)d_in[3];
    const float* b2 = (const float*)d_in[4];
    const float* W3 = (const float*)d_in[5];
    const float* b3 = (const float*)d_in[6];
    const float* W4 = (const float*)d_in[7];
    const float* b4 = (const float*)d_in[8];
    const float* W5 = (const float*)d_in[9];
    const float* b5 = (const float*)d_in[10];
    float* out = (float*)d_out;

    int nrows = in_sizes[0] / 7;

    int sms = 0;
    if (cudaDeviceGetAttribute(&sms, cudaDevAttrMultiProcessorCount, 0) != cudaSuccess || sms <= 0)
        sms = 148;
    int blocks = sms * 6;

    mlp_persist2_kernel<<<blocks, 256>>>(X, out, nrows,
                                         W1, b1, W2, b2, W3, b3, W4, b4, W5, b5);
}

// round 13
// speedup vs baseline: 1.1334x; 1.1334x over previous
#include <cuda_runtime.h>
#include <math.h>
#include <stdint.h>

// ---------------------------------------------------------------------------
// Hybrid persistent kernel: TMA pipeline + register-prefetched direct-LDG.
//   Super-stage = 512 row-quads: first 256 arrive via TMA (2-stage 28672-B
//   pipeline, R8 config); the second 256 are loaded directly (uncoalesced
//   LDG.128, L1-cached) but PREFETCHED ONE SUPER-STAGE AHEAD into registers,
//   so their DRAM latency hides behind a full stage of smem work.
//   The two load paths saturate different units (async proxy vs L1tex
//   wavefronts) and run concurrently. 3 blocks/SM x 256 threads.
// ---------------------------------------------------------------------------

#define SS_QUADS      512
#define SM_QUADS      256
#define STAGE_BYTES   (SM_QUADS * 112)       // 28672 B
#define NSTAGE        2
#define BLOCKS_PER_SM 3

__device__ __forceinline__ uint32_t smem_u32(const void* p) {
    uint32_t a;
    asm("{ .reg .u64 t; cvta.to.shared.u64 t, %1; cvt.u32.u64 %0, t; }"
        : "=r"(a) : "l"(p));
    return a;
}

#define MBAR_INIT(addr, cnt) \
    asm volatile("mbarrier.init.shared.b64 [%0], %1;" :: "r"(addr), "r"(cnt) : "memory")

#define MBAR_EXPECT_TX(addr, bytes) \
    asm volatile("mbarrier.arrive.expect_tx.shared.b64 _, [%0], %1;" \
                 :: "r"(addr), "r"(bytes) : "memory")

#define MBAR_ARRIVE(addr) \
    asm volatile("mbarrier.arrive.shared.b64 _, [%0];" :: "r"(addr) : "memory")

#define MBAR_WAIT(addr, parity) do {                                          \
    uint32_t _m = (addr), _p = (parity), _done;                               \
    asm volatile(                                                             \
        "{\n\t.reg .pred p;\n\t"                                              \
        "mbarrier.try_wait.parity.acquire.cta.shared::cta.b64 p, [%1], %2;\n\t"\
        "selp.b32 %0, 1, 0, p;\n\t}"                                          \
        : "=r"(_done) : "r"(_m), "r"(_p) : "memory");                         \
    if (!_done) {                                                             \
        asm volatile(                                                         \
            "{\n\t.reg .pred P1;\n\t"                                         \
            "WL_%=:\n\t"                                                      \
            "mbarrier.try_wait.parity.acquire.cta.shared::cta.b64 P1, [%0], %1, 0x989680;\n\t" \
            "@P1 bra.uni WD_%=;\n\t"                                          \
            "bra.uni WL_%=;\n\t"                                              \
            "WD_%=:\n\t}"                                                     \
            :: "r"(_m), "r"(_p) : "memory");                                  \
    }                                                                         \
} while (0)

#define BULK_G2S(dst_smem, src_gmem, bytes, mbar) \
    asm volatile("cp.async.bulk.shared::cluster.global.mbarrier::complete_tx::bytes " \
                 "[%0], [%1], %2, [%3];" \
                 :: "r"(dst_smem), "l"(src_gmem), "r"(bytes), "r"(mbar) : "memory")

__device__ __forceinline__ float4 quad_sigmoid(
    float4 p0, float4 p1, float4 p2, float4 p3, float4 p4, float4 p5, float4 p6,
    float w0, float w1, float w2, float w3, float w4, float w5, float w6, float be)
{
    float f[28];
    f[0]=p0.x; f[1]=p0.y; f[2]=p0.z; f[3]=p0.w;
    f[4]=p1.x; f[5]=p1.y; f[6]=p1.z; f[7]=p1.w;
    f[8]=p2.x; f[9]=p2.y; f[10]=p2.z; f[11]=p2.w;
    f[12]=p3.x; f[13]=p3.y; f[14]=p3.z; f[15]=p3.w;
    f[16]=p4.x; f[17]=p4.y; f[18]=p4.z; f[19]=p4.w;
    f[20]=p5.x; f[21]=p5.y; f[22]=p5.z; f[23]=p5.w;
    f[24]=p6.x; f[25]=p6.y; f[26]=p6.z; f[27]=p6.w;

    float r[4];
    #pragma unroll
    for (int r4 = 0; r4 < 4; r4++) {
        const float* x = f + r4 * 7;
        float z = be;
        z = fmaf(x[0], w0, z);
        z = fmaf(x[1], w1, z);
        z = fmaf(x[2], w2, z);
        z = fmaf(x[3], w3, z);
        z = fmaf(x[4], w4, z);
        z = fmaf(x[5], w5, z);
        z = fmaf(x[6], w6, z);
        r[r4] = 1.0f / (1.0f + __expf(-z));
    }
    float4 o; o.x = r[0]; o.y = r[1]; o.z = r[2]; o.w = r[3];
    return o;
}

__global__ void __launch_bounds__(256, BLOCKS_PER_SM)
mlp_hybrid2_kernel(const float* __restrict__ X, float* __restrict__ out, int nrows,
                   const float* __restrict__ W1, const float* __restrict__ b1,
                   const float* __restrict__ W2, const float* __restrict__ b2,
                   const float* __restrict__ W3, const float* __restrict__ b3,
                   const float* __restrict__ W4, const float* __restrict__ b4,
                   const float* __restrict__ W5, const float* __restrict__ b5)
{
    extern __shared__ __align__(128) unsigned char smem[];
    __shared__ float s_weff[8];

    const int tid  = threadIdx.x;
    const int lane = tid & 31;
    const uint32_t sbase = smem_u32(smem);
    const uint32_t mbar0 = sbase + NSTAGE * STAGE_BYTES;

    const long long total_quads = (long long)(nrows >> 2);
    const long long nss = (total_quads + SS_QUADS - 1) / SS_QUADS;

    // balanced contiguous partition of super-stages across blocks
    const long long g    = gridDim.x;
    const long long base = nss / g;
    const long long rem  = nss % g;
    const long long bidx = blockIdx.x;
    const long long my_cnt   = base + (bidx < rem ? 1 : 0);
    const long long my_start = bidx * base + (bidx < rem ? bidx : rem);

    if (tid == 0) {
        #pragma unroll
        for (int i = 0; i < NSTAGE; i++) {
            MBAR_INIT(mbar0 + 16 * i,     1u);   // full: TMA tx
            MBAR_INIT(mbar0 + 16 * i + 8, 8u);   // empty: 8 warp reps
        }
        asm volatile("fence.proxy.async.shared::cta;" ::: "memory");

        // prologue TMAs (smem halves of first two local super-stages)
        #pragma unroll
        for (int k = 0; k < NSTAGE; k++) {
            if (k < my_cnt) {
                long long q0 = (my_start + k) * SS_QUADS;
                long long qn = total_quads - q0;
                long long qsm = qn < SM_QUADS ? qn : SM_QUADS;
                uint32_t bytes = (uint32_t)(qsm * 112);
                MBAR_EXPECT_TX(mbar0 + 16 * k, bytes);
                BULK_G2S(sbase + k * STAGE_BYTES,
                         (const void*)(X + q0 * 28), bytes, mbar0 + 16 * k);
            }
        }

        // ---- compose 5 linears into 7->1 affine (overlaps in-flight TMAs) ----
        const float c50 = W5[0], c51 = W5[1];

        const float w45_0 = fmaf(W4[0], c50, W4[1] * c51);
        const float w45_1 = fmaf(W4[2], c50, W4[3] * c51);
        const float w45_2 = fmaf(W4[4], c50, W4[5] * c51);

        const float w345_0 = fmaf(W3[0],  w45_0, fmaf(W3[1],  w45_1, W3[2]  * w45_2));
        const float w345_1 = fmaf(W3[3],  w45_0, fmaf(W3[4],  w45_1, W3[5]  * w45_2));
        const float w345_2 = fmaf(W3[6],  w45_0, fmaf(W3[7],  w45_1, W3[8]  * w45_2));
        const float w345_3 = fmaf(W3[9],  w45_0, fmaf(W3[10], w45_1, W3[11] * w45_2));

        const float w2345_0 = fmaf(W2[0],  w345_0, fmaf(W2[1],  w345_1, fmaf(W2[2],  w345_2, W2[3]  * w345_3)));
        const float w2345_1 = fmaf(W2[4],  w345_0, fmaf(W2[5],  w345_1, fmaf(W2[6],  w345_2, W2[7]  * w345_3)));
        const float w2345_2 = fmaf(W2[8],  w345_0, fmaf(W2[9],  w345_1, fmaf(W2[10], w345_2, W2[11] * w345_3)));
        const float w2345_3 = fmaf(W2[12], w345_0, fmaf(W2[13], w345_1, fmaf(W2[14], w345_2, W2[15] * w345_3)));
        const float w2345_4 = fmaf(W2[16], w345_0, fmaf(W2[17], w345_1, fmaf(W2[18], w345_2, W2[19] * w345_3)));

        #pragma unroll
        for (int i = 0; i < 7; i++) {
            s_weff[i] = fmaf(W1[i*5 + 0], w2345_0,
                        fmaf(W1[i*5 + 1], w2345_1,
                        fmaf(W1[i*5 + 2], w2345_2,
                        fmaf(W1[i*5 + 3], w2345_3,
                             W1[i*5 + 4] * w2345_4))));
        }

        float be = b5[0];
        be = fmaf(b4[0], c50, be);
        be = fmaf(b4[1], c51, be);
        be = fmaf(b3[0], w45_0, be);
        be = fmaf(b3[1], w45_1, be);
        be = fmaf(b3[2], w45_2, be);
        be = fmaf(b2[0], w345_0, be);
        be = fmaf(b2[1], w345_1, be);
        be = fmaf(b2[2], w345_2, be);
        be = fmaf(b2[3], w345_3, be);
        be = fmaf(b1[0], w2345_0, be);
        be = fmaf(b1[1], w2345_1, be);
        be = fmaf(b1[2], w2345_2, be);
        be = fmaf(b1[3], w2345_3, be);
        be = fmaf(b1[4], w2345_4, be);
        s_weff[7] = be;
    }

    // ---- per-thread prologue: prefetch direct quads of FIRST local stage ----
    float4 pr0, pr1, pr2, pr3, pr4, pr5, pr6;
    int  qdir_cur = 0;
    long long dir_base_cur = 0;
    if (my_cnt > 0) {
        const long long q0 = my_start * SS_QUADS;
        const long long qn = (total_quads - q0 < SS_QUADS) ? (total_quads - q0) : SS_QUADS;
        const int qsm = (int)(qn < SM_QUADS ? qn : SM_QUADS);
        qdir_cur = (int)(qn - qsm);
        dir_base_cur = q0 + qsm;
        if (tid < qdir_cur) {
            const float4* dp = reinterpret_cast<const float4*>(X + (dir_base_cur + tid) * 28);
            pr0 = dp[0]; pr1 = dp[1]; pr2 = dp[2]; pr3 = dp[3];
            pr4 = dp[4]; pr5 = dp[5]; pr6 = dp[6];
        }
    }

    __syncthreads();

    const float w0 = s_weff[0], w1 = s_weff[1], w2 = s_weff[2], w3 = s_weff[3];
    const float w4 = s_weff[4], w5 = s_weff[5], w6 = s_weff[6], be = s_weff[7];

    float4* outv = reinterpret_cast<float4*>(out);

    for (long long j = 0; j < my_cnt; j++) {
        const long long s  = my_start + j;
        const long long q0 = s * SS_QUADS;
        const long long qn = (total_quads - q0 < SS_QUADS) ? (total_quads - q0) : SS_QUADS;
        const int qsm = (int)(qn < SM_QUADS ? qn : SM_QUADS);

        const int slot  = (int)(j & 1);
        const int phase = (int)((j >> 1) & 1);
        const uint32_t full_b  = mbar0 + 16 * slot;
        const uint32_t empty_b = full_b + 8;

        // ---- 1) consume direct registers prefetched one stage ago (no stall) ----
        if (tid < qdir_cur) {
            float4 o = quad_sigmoid(pr0, pr1, pr2, pr3, pr4, pr5, pr6,
                                    w0, w1, w2, w3, w4, w5, w6, be);
            outv[dir_base_cur + tid] = o;
        }

        // ---- 2) issue prefetch for stage j+1's direct quads ----
        if (j + 1 < my_cnt) {
            const long long q01 = (s + 1) * SS_QUADS;
            const long long qn1 = (total_quads - q01 < SS_QUADS) ? (total_quads - q01) : SS_QUADS;
            const int qsm1 = (int)(qn1 < SM_QUADS ? qn1 : SM_QUADS);
            const int qdir1 = (int)(qn1 - qsm1);
            const long long db1 = q01 + qsm1;
            if (tid < qdir1) {
                const float4* dp = reinterpret_cast<const float4*>(X + (db1 + tid) * 28);
                pr0 = dp[0]; pr1 = dp[1]; pr2 = dp[2]; pr3 = dp[3];
                pr4 = dp[4]; pr5 = dp[5]; pr6 = dp[6];
            }
            qdir_cur = qdir1;
            dir_base_cur = db1;
        } else {
            qdir_cur = 0;
        }

        // ---- 3) TMA-fed smem path: quads [q0, q0+qsm) ----
        MBAR_WAIT(full_b, phase);

        if (tid < qsm) {
            const float4* xq = reinterpret_cast<const float4*>(
                smem + (size_t)slot * STAGE_BYTES + (size_t)tid * 112);
            float4 p0 = xq[0], p1 = xq[1], p2 = xq[2], p3 = xq[3];
            float4 p4 = xq[4], p5 = xq[5], p6 = xq[6];
            float4 o = quad_sigmoid(p0, p1, p2, p3, p4, p5, p6,
                                    w0, w1, w2, w3, w4, w5, w6, be);
            outv[q0 + tid] = o;
        }

        __syncwarp();
        if (lane == 0) MBAR_ARRIVE(empty_b);

        // ---- 4) producer: refill this slot for stage j+2 ----
        if (tid == 0) {
            const long long j2 = j + NSTAGE;
            if (j2 < my_cnt) {
                MBAR_WAIT(empty_b, phase);
                const long long q2 = (my_start + j2) * SS_QUADS;
                long long qn2 = total_quads - q2;
                long long qsm2 = qn2 < SM_QUADS ? qn2 : SM_QUADS;
                uint32_t bytes = (uint32_t)(qsm2 * 112);
                MBAR_EXPECT_TX(full_b, bytes);
                BULK_G2S(sbase + slot * STAGE_BYTES,
                         (const void*)(X + q2 * 28), bytes, full_b);
            }
        }
    }

    // Tail rows (nrows % 4) — zero for 4M rows; kept for safety.
    if (blockIdx.x == 0 && tid == 0) {
        for (long long rr = total_quads << 2; rr < nrows; rr++) {
            const float* x = X + rr * 7;
            float z = be;
            z = fmaf(x[0], w0, z);
            z = fmaf(x[1], w1, z);
            z = fmaf(x[2], w2, z);
            z = fmaf(x[3], w3, z);
            z = fmaf(x[4], w4, z);
            z = fmaf(x[5], w5, z);
            z = fmaf(x[6], w6, z);
            out[rr] = 1.0f / (1.0f + __expf(-z));
        }
    }
}

extern "C" void kernel_launch(void* const* d_in, const int* in_sizes, int n_in,
                              void* d_out, int out_size)
{
    const float* X  = (const float*)d_in[0];
    const float* W1 = (const float*)d_in[1];
    const float* b1 = (const float*)d_in[2];
    const float* W2 = (const float*)d_in[3];
    const float* b2 = (const float*)d_in[4];
    const float* W3 = (const float*)d_in[5];
    const float* b3 = (const float*)d_in[6];
    const float* W4 = (const float*)d_in[7];
    const float* b4 = (const float*)d_in[8];
    const float* W5 = (const float*)d_in[9];
    const float* b5 = (const float*)d_in[10];
    float* out = (float*)d_out;

    int nrows = in_sizes[0] / 7;

    const int smem_bytes = NSTAGE * STAGE_BYTES + NSTAGE * 16;  // 57376 B

    static bool attr_done = false;
    if (!attr_done) {
        cudaFuncSetAttribute(mlp_hybrid2_kernel,
                             cudaFuncAttributeMaxDynamicSharedMemorySize, smem_bytes);
        attr_done = true;
    }

    int sms = 0;
    if (cudaDeviceGetAttribute(&sms, cudaDevAttrMultiProcessorCount, 0) != cudaSuccess || sms <= 0)
        sms = 148;

    mlp_hybrid2_kernel<<<sms * BLOCKS_PER_SM, 256, smem_bytes>>>(
        X, out, nrows, W1, b1, W2, b2, W3, b3, W4, b4, W5, b5);
}

// round 14
// speedup vs baseline: 1.2261x; 1.0817x over previous
#include <cuda_runtime.h>
#include <math.h>
#include <stdint.h>

// ---------------------------------------------------------------------------
// FLAT-LAUNCH TMA kernel: one block = one 28672-B stage (256 row-quads),
// 3907 one-shot blocks. Each block issues its single TMA immediately on
// schedule (CLC work-stealing keeps ~7 fills in flight per SM, no refill
// gating, no lock-step). Compose of the 5 tiny linears overlaps the fill.
//   consume: 4 rows/thread via conflict-free LDS (tid*112), 28 FMA +
//   sigmoid, coalesced STG.128, exit.
// ---------------------------------------------------------------------------

#define STAGE_QUADS   256
#define STAGE_BYTES   (STAGE_QUADS * 112)    // 28672 B

__device__ __forceinline__ uint32_t smem_u32(const void* p) {
    uint32_t a;
    asm("{ .reg .u64 t; cvta.to.shared.u64 t, %1; cvt.u32.u64 %0, t; }"
        : "=r"(a) : "l"(p));
    return a;
}

#define MBAR_INIT(addr, cnt) \
    asm volatile("mbarrier.init.shared.b64 [%0], %1;" :: "r"(addr), "r"(cnt) : "memory")

#define MBAR_EXPECT_TX(addr, bytes) \
    asm volatile("mbarrier.arrive.expect_tx.shared.b64 _, [%0], %1;" \
                 :: "r"(addr), "r"(bytes) : "memory")

#define MBAR_WAIT(addr, parity) do {                                          \
    uint32_t _m = (addr), _p = (parity), _done;                               \
    asm volatile(                                                             \
        "{\n\t.reg .pred p;\n\t"                                              \
        "mbarrier.try_wait.parity.acquire.cta.shared::cta.b64 p, [%1], %2;\n\t"\
        "selp.b32 %0, 1, 0, p;\n\t}"                                          \
        : "=r"(_done) : "r"(_m), "r"(_p) : "memory");                         \
    if (!_done) {                                                             \
        asm volatile(                                                         \
            "{\n\t.reg .pred P1;\n\t"                                         \
            "WL_%=:\n\t"                                                      \
            "mbarrier.try_wait.parity.acquire.cta.shared::cta.b64 P1, [%0], %1, 0x989680;\n\t" \
            "@P1 bra.uni WD_%=;\n\t"                                          \
            "bra.uni WL_%=;\n\t"                                              \
            "WD_%=:\n\t}"                                                     \
            :: "r"(_m), "r"(_p) : "memory");                                  \
    }                                                                         \
} while (0)

#define BULK_G2S(dst_smem, src_gmem, bytes, mbar) \
    asm volatile("cp.async.bulk.shared::cluster.global.mbarrier::complete_tx::bytes " \
                 "[%0], [%1], %2, [%3];" \
                 :: "r"(dst_smem), "l"(src_gmem), "r"(bytes), "r"(mbar) : "memory")

__global__ void __launch_bounds__(256)
mlp_flat_tma_kernel(const float* __restrict__ X, float* __restrict__ out, int nrows,
                    const float* __restrict__ W1, const float* __restrict__ b1,
                    const float* __restrict__ W2, const float* __restrict__ b2,
                    const float* __restrict__ W3, const float* __restrict__ b3,
                    const float* __restrict__ W4, const float* __restrict__ b4,
                    const float* __restrict__ W5, const float* __restrict__ b5)
{
    extern __shared__ __align__(128) unsigned char smem[];
    __shared__ float s_weff[8];

    const int tid = threadIdx.x;
    const uint32_t sbase  = smem_u32(smem);
    const uint32_t full_b = sbase + STAGE_BYTES;     // 8B mbarrier after buffer

    const long long total_quads = (long long)(nrows >> 2);
    const long long q0 = (long long)blockIdx.x * STAGE_QUADS;
    const int quads = (int)((total_quads - q0 < STAGE_QUADS) ? (total_quads - q0)
                                                             : STAGE_QUADS);

    if (tid == 0) {
        // 1) barrier + TMA issue — first thing the block does on schedule
        MBAR_INIT(full_b, 1u);
        asm volatile("fence.proxy.async.shared::cta;" ::: "memory");
        MBAR_EXPECT_TX(full_b, (uint32_t)(quads * 112));
        BULK_G2S(sbase, (const void*)(X + q0 * 28),
                 (uint32_t)(quads * 112), full_b);

        // 2) compose 5 linears into 7->1 affine (overlaps the TMA fill;
        //    W/b are tiny and L2-resident after the first wave)
        const float c50 = W5[0], c51 = W5[1];

        const float w45_0 = fmaf(W4[0], c50, W4[1] * c51);
        const float w45_1 = fmaf(W4[2], c50, W4[3] * c51);
        const float w45_2 = fmaf(W4[4], c50, W4[5] * c51);

        const float w345_0 = fmaf(W3[0],  w45_0, fmaf(W3[1],  w45_1, W3[2]  * w45_2));
        const float w345_1 = fmaf(W3[3],  w45_0, fmaf(W3[4],  w45_1, W3[5]  * w45_2));
        const float w345_2 = fmaf(W3[6],  w45_0, fmaf(W3[7],  w45_1, W3[8]  * w45_2));
        const float w345_3 = fmaf(W3[9],  w45_0, fmaf(W3[10], w45_1, W3[11] * w45_2));

        const float w2345_0 = fmaf(W2[0],  w345_0, fmaf(W2[1],  w345_1, fmaf(W2[2],  w345_2, W2[3]  * w345_3)));
        const float w2345_1 = fmaf(W2[4],  w345_0, fmaf(W2[5],  w345_1, fmaf(W2[6],  w345_2, W2[7]  * w345_3)));
        const float w2345_2 = fmaf(W2[8],  w345_0, fmaf(W2[9],  w345_1, fmaf(W2[10], w345_2, W2[11] * w345_3)));
        const float w2345_3 = fmaf(W2[12], w345_0, fmaf(W2[13], w345_1, fmaf(W2[14], w345_2, W2[15] * w345_3)));
        const float w2345_4 = fmaf(W2[16], w345_0, fmaf(W2[17], w345_1, fmaf(W2[18], w345_2, W2[19] * w345_3)));

        #pragma unroll
        for (int i = 0; i < 7; i++) {
            s_weff[i] = fmaf(W1[i*5 + 0], w2345_0,
                        fmaf(W1[i*5 + 1], w2345_1,
                        fmaf(W1[i*5 + 2], w2345_2,
                        fmaf(W1[i*5 + 3], w2345_3,
                             W1[i*5 + 4] * w2345_4))));
        }

        float be = b5[0];
        be = fmaf(b4[0], c50, be);
        be = fmaf(b4[1], c51, be);
        be = fmaf(b3[0], w45_0, be);
        be = fmaf(b3[1], w45_1, be);
        be = fmaf(b3[2], w45_2, be);
        be = fmaf(b2[0], w345_0, be);
        be = fmaf(b2[1], w345_1, be);
        be = fmaf(b2[2], w345_2, be);
        be = fmaf(b2[3], w345_3, be);
        be = fmaf(b1[0], w2345_0, be);
        be = fmaf(b1[1], w2345_1, be);
        be = fmaf(b1[2], w2345_2, be);
        be = fmaf(b1[3], w2345_3, be);
        be = fmaf(b1[4], w2345_4, be);
        s_weff[7] = be;
    }
    __syncthreads();   // s_weff visible; barrier init ordered before waits

    const float w0 = s_weff[0], w1 = s_weff[1], w2 = s_weff[2], w3 = s_weff[3];
    const float w4 = s_weff[4], w5 = s_weff[5], w6 = s_weff[6], be = s_weff[7];

    MBAR_WAIT(full_b, 0);

    if (tid < quads) {
        const float4* xq = reinterpret_cast<const float4*>(smem + (size_t)tid * 112);
        float4 p0 = xq[0], p1 = xq[1], p2 = xq[2], p3 = xq[3];
        float4 p4 = xq[4], p5 = xq[5], p6 = xq[6];

        float f[28];
        f[0]=p0.x; f[1]=p0.y; f[2]=p0.z; f[3]=p0.w;
        f[4]=p1.x; f[5]=p1.y; f[6]=p1.z; f[7]=p1.w;
        f[8]=p2.x; f[9]=p2.y; f[10]=p2.z; f[11]=p2.w;
        f[12]=p3.x; f[13]=p3.y; f[14]=p3.z; f[15]=p3.w;
        f[16]=p4.x; f[17]=p4.y; f[18]=p4.z; f[19]=p4.w;
        f[20]=p5.x; f[21]=p5.y; f[22]=p5.z; f[23]=p5.w;
        f[24]=p6.x; f[25]=p6.y; f[26]=p6.z; f[27]=p6.w;

        float r[4];
        #pragma unroll
        for (int r4 = 0; r4 < 4; r4++) {
            const float* x = f + r4 * 7;
            float z = be;
            z = fmaf(x[0], w0, z);
            z = fmaf(x[1], w1, z);
            z = fmaf(x[2], w2, z);
            z = fmaf(x[3], w3, z);
            z = fmaf(x[4], w4, z);
            z = fmaf(x[5], w5, z);
            z = fmaf(x[6], w6, z);
            r[r4] = 1.0f / (1.0f + __expf(-z));
        }

        float4 o;
        o.x = r[0]; o.y = r[1]; o.z = r[2]; o.w = r[3];
        reinterpret_cast<float4*>(out)[q0 + tid] = o;
    }

    // Tail rows (nrows % 4) — zero for 4M rows; kept for safety.
    if (blockIdx.x == 0 && tid == 0) {
        for (long long rr = total_quads << 2; rr < nrows; rr++) {
            const float* x = X + rr * 7;
            float z = be;
            z = fmaf(x[0], w0, z);
            z = fmaf(x[1], w1, z);
            z = fmaf(x[2], w2, z);
            z = fmaf(x[3], w3, z);
            z = fmaf(x[4], w4, z);
            z = fmaf(x[5], w5, z);
            z = fmaf(x[6], w6, z);
            out[rr] = 1.0f / (1.0f + __expf(-z));
        }
    }
}

extern "C" void kernel_launch(void* const* d_in, const int* in_sizes, int n_in,
                              void* d_out, int out_size)
{
    const float* X  = (const float*)d_in[0];
    const float* W1 = (const float*)d_in[1];
    const float* b1 = (const float*)d_in[2];
    const float* W2 = (const float*)d_in[3];
    const float* b2 = (const float*)d_in[4];
    const float* W3 = (const float*)d_in[5];
    const float* b3 = (const float*)d_in[6];
    const float* W4 = (const float*)d_in[7];
    const float* b4 = (const float*)d_in[8];
    const float* W5 = (const float*)d_in[9];
    const float* b5 = (const float*)d_in[10];
    float* out = (float*)d_out;

    int nrows = in_sizes[0] / 7;

    const int smem_bytes = STAGE_BYTES + 16;   // buffer + mbarrier

    static bool attr_done = false;
    if (!attr_done) {
        cudaFuncSetAttribute(mlp_flat_tma_kernel,
                             cudaFuncAttributeMaxDynamicSharedMemorySize, smem_bytes);
        attr_done = true;
    }

    long long nquads = (long long)(nrows / 4);
    int blocks = (int)((nquads + STAGE_QUADS - 1) / STAGE_QUADS);

    mlp_flat_tma_kernel<<<blocks, 256, smem_bytes>>>(
        X, out, nrows, W1, b1, W2, b2, W3, b3, W4, b4, W5, b5);
}